// round 8
// baseline (speedup 1.0000x reference)
#include <cuda_runtime.h>
#include <cstdint>

// out[b] = sum_i cos(x[b,i]) * w[i] + bias ;  x: [1048576, 32] f32 (128B/row).
//
// cp.async version: each warp stages its own 4KB (32 rows = 8 groups) into
// SMEM via 8x cp.async.cg (16B/lane), waits only on its own group
// (wait_group 0 + syncwarp; per-warp regions => no __syncthreads), then
// computes from SMEM with conflict-free LDS.128. Bytes-in-flight live in
// SMEM, not registers: MLP~8/thread at ~32 regs.
//
// Group = 4 rows = 512B; lane l holds float4 #l; chunk=l&7 picks weight quad;
// 3-step shfl_xor in each 8-lane subgroup yields the 4 row sums.

#define TILE_BYTES   32768          // 256 rows per CTA (8 warps * 32 rows)
#define WARP_BYTES   4096           // 32 rows per warp = 8 groups

__device__ __forceinline__ float group_dot(const float4& xv, const float4& wv)
{
    return __cosf(xv.x) * wv.x + __cosf(xv.y) * wv.y
         + __cosf(xv.z) * wv.z + __cosf(xv.w) * wv.w;
}

__device__ __forceinline__ float reduce8(float s)
{
    s += __shfl_xor_sync(0xffffffffu, s, 1);
    s += __shfl_xor_sync(0xffffffffu, s, 2);
    s += __shfl_xor_sync(0xffffffffu, s, 4);
    return s;
}

__global__ void __launch_bounds__(256) hybrid_regression_kernel(
    const char*  __restrict__ x,
    const float* __restrict__ w,
    const float* __restrict__ bias,
    float*       __restrict__ out,
    int nrows)
{
    __shared__ __align__(16) char tile[TILE_BYTES];

    int tid   = threadIdx.x;
    int wid   = tid >> 5;
    int lane  = tid & 31;
    int chunk = lane & 7;
    int sub   = lane >> 3;

    int row0 = blockIdx.x * 256 + wid * 32;      // first row this warp owns
    if (row0 >= nrows) return;

    const char* gsrc = x + (size_t)row0 * 128;
    char*       ssrc = tile + wid * WARP_BYTES;

    float4 wv = reinterpret_cast<const float4*>(w)[chunk];
    float  bb = bias[0];

    if (row0 + 32 <= nrows) {
        // stage 4KB: 8 rounds x (32 lanes x 16B) = fully coalesced 512B bursts
        #pragma unroll
        for (int i = 0; i < 8; ++i) {
            uint32_t saddr = (uint32_t)__cvta_generic_to_shared(ssrc + i * 512 + lane * 16);
            const void* gaddr = gsrc + i * 512 + lane * 16;
            asm volatile("cp.async.cg.shared.global [%0], [%1], 16;\n"
                         :: "r"(saddr), "l"(gaddr));
        }
        asm volatile("cp.async.commit_group;\n");
        asm volatile("cp.async.wait_group 0;\n" ::: "memory");
        __syncwarp();

        // compute from SMEM: group g at bytes [g*512, +512), lane l -> float4 #l
        const float4* sg = reinterpret_cast<const float4*>(ssrc);
        float s[8];
        #pragma unroll
        for (int g = 0; g < 8; ++g) {
            float4 xv = sg[g * 32 + lane];
            s[g] = reduce8(group_dot(xv, wv));
        }

        if (chunk == 0) {
            int r = row0 + sub;
            #pragma unroll
            for (int g = 0; g < 8; ++g)
                __stcs(out + r + g * 4, s[g] + bb);   // (R7 bug: bias was missing)
        }
    } else {
        // tail (not hit for B=1048576): direct-gmem fallback, 1 group at a time
        const float4* x4 = reinterpret_cast<const float4*>(gsrc);
        int rem_groups = (nrows - row0) / 4;
        for (int g = 0; g < rem_groups; ++g) {
            float4 xv = __ldcs(x4 + g * 32 + lane);
            float s = reduce8(group_dot(xv, wv));
            if (chunk == 0) out[row0 + g * 4 + sub] = s + bb;
        }
        return;
    }
}

extern "C" void kernel_launch(void* const* d_in, const int* in_sizes, int n_in,
                              void* d_out, int out_size)
{
    const char*  x    = (const char*)d_in[0];    // [B, 32] f32
    // d_in[1] = theta: mathematically dead (RZ phase leaves <Z> unchanged)
    const float* w    = (const float*)d_in[2];   // [1, 32]
    const float* b    = (const float*)d_in[3];   // [1]
    float* out        = (float*)d_out;

    int nrows = in_sizes[0] / 32;                // 1048576

    int threads = 256;
    int rows_per_block = 256;
    int blocks = (nrows + rows_per_block - 1) / rows_per_block;   // 4096

    hybrid_regression_kernel<<<blocks, threads>>>(x, w, b, out, nrows);
}

// round 9
// speedup vs baseline: 1.0809x; 1.0809x over previous
#include <cuda_runtime.h>

// out[b] = sum_i cos(x[b,i]) * w[i] + bias ;  x: [1048576, 32] f32.
//
// One-shot warps (R5 structure, finer blocks): each warp processes exactly ONE
// batch of 4 groups (4 rows/group = 2KB), 4 independent front-batched LDG.128
// (MLP=4), reduces, stores, exits. 128-thread blocks -> 16384 blocks: maximum
// scheduler re-balancing granularity, minimal straggler-tail quantum.
//
// Lane l holds float4 #l of a 512B group; chunk = l&7 selects the weight quad;
// 3-step shfl_xor within each 8-lane subgroup yields the 4 row sums.

__device__ __forceinline__ float group_dot(const float4& xv, const float4& wv)
{
    return __cosf(xv.x) * wv.x + __cosf(xv.y) * wv.y
         + __cosf(xv.z) * wv.z + __cosf(xv.w) * wv.w;
}

__device__ __forceinline__ float reduce8(float s)
{
    s += __shfl_xor_sync(0xffffffffu, s, 1);
    s += __shfl_xor_sync(0xffffffffu, s, 2);
    s += __shfl_xor_sync(0xffffffffu, s, 4);
    return s;
}

__global__ void __launch_bounds__(128, 16) hybrid_regression_kernel(
    const float4* __restrict__ x4,
    const float*  __restrict__ w,
    const float*  __restrict__ bias,
    float*        __restrict__ out,
    int ngroups)
{
    int gtid  = blockIdx.x * blockDim.x + threadIdx.x;
    int warp  = gtid >> 5;
    int lane  = gtid & 31;
    int chunk = lane & 7;
    int sub   = lane >> 3;

    int g0 = warp * 4;                      // 4 groups per warp, one shot
    if (g0 >= ngroups) return;

    float4 wv = reinterpret_cast<const float4*>(w)[chunk];

    const float4* p = x4 + (size_t)g0 * 32 + lane;

    if (g0 + 4 <= ngroups) {
        // 4 independent coalesced 512B loads, front-batched (MLP=4)
        float4 xv0 = __ldcs(p +  0);
        float4 xv1 = __ldcs(p + 32);
        float4 xv2 = __ldcs(p + 64);
        float4 xv3 = __ldcs(p + 96);

        float bb = bias[0];

        float s0 = reduce8(group_dot(xv0, wv));
        float s1 = reduce8(group_dot(xv1, wv));
        float s2 = reduce8(group_dot(xv2, wv));
        float s3 = reduce8(group_dot(xv3, wv));

        if (chunk == 0) {
            int r = g0 * 4 + sub;
            out[r +  0] = s0 + bb;
            out[r +  4] = s1 + bb;
            out[r +  8] = s2 + bb;
            out[r + 12] = s3 + bb;
        }
    } else {
        // tail (not hit for B=1048576, kept for generality)
        float bb = bias[0];
        for (int g = g0; g < ngroups; ++g) {
            float4 xv = __ldcs(x4 + (size_t)g * 32 + lane);
            float s = reduce8(group_dot(xv, wv));
            if (chunk == 0) out[g * 4 + sub] = s + bb;
        }
    }
}

extern "C" void kernel_launch(void* const* d_in, const int* in_sizes, int n_in,
                              void* d_out, int out_size)
{
    const float* x    = (const float*)d_in[0];   // [B, 32]
    // d_in[1] = theta: mathematically dead (RZ phase leaves <Z> unchanged)
    const float* w    = (const float*)d_in[2];   // [1, 32]
    const float* b    = (const float*)d_in[3];   // [1]
    float* out        = (float*)d_out;

    int batch   = in_sizes[0] / 32;
    int ngroups = batch / 4;                      // 262144

    int threads = 128;
    int warps_per_block   = threads / 32;         // 4
    int groups_per_block  = warps_per_block * 4;  // 16
    int blocks = (ngroups + groups_per_block - 1) / groups_per_block;  // 16384

    hybrid_regression_kernel<<<blocks, threads>>>(
        (const float4*)x, w, b, out, ngroups);
}